// round 1
// baseline (speedup 1.0000x reference)
#include <cuda_runtime.h>
#include <cuda_bf16.h>
#include <math.h>

#define BB   16
#define NN   128
#define FIN  128
#define FOUT 256
#define EOUT 64
#define BIN  14
#define BOUT 64
#define CI   64
#define LL1  256
#define CATW (2*CI + FOUT)   // 384

// ---------------- scratch ----------------
__device__ float d_h  [BB*NN*FOUT];       // 2 MB
__device__ float d_ha1[BB*NN*EOUT];
__device__ float d_ha2[BB*NN*EOUT];
__device__ float d_hc [BB*NN];
__device__ float d_s1 [BB*NN];
__device__ float d_s2 [BB*NN];
__device__ float d_att[BB*NN*NN];         // 1 MB
__device__ float d_hn [BB*NN*NN];         // 1 MB
__device__ float d_pre[2][BB*NN*CI];
__device__ float d_cat[BB*NN*CATW];       // 3 MB

__device__ __forceinline__ float lrelu(float v) { return v > 0.f ? v : 0.01f * v; }

// ---------------- K1: h = x @ W ----------------
__global__ void k1_h(const float* __restrict__ x, const float* __restrict__ W) {
    int row = blockIdx.x;          // b*NN + n  (2048)
    int f   = threadIdx.x;         // 256
    __shared__ float xs[FIN];
    if (f < FIN) xs[f] = x[row*FIN + f];
    __syncthreads();
    float acc = 0.f;
    #pragma unroll 8
    for (int k = 0; k < FIN; k++) acc += xs[k] * W[k*FOUT + f];
    d_h[row*FOUT + f] = acc;
}

// ---------------- K2: ha1/ha2/hc/s1 per row ----------------
__global__ void k2_ha(const float* __restrict__ a, const float* __restrict__ fc_w,
                      const float* __restrict__ fcc_w) {
    int row = blockIdx.x;          // 2048
    int k   = threadIdx.x;         // 64
    __shared__ float hs[FOUT];
    __shared__ float red[64];
    for (int i = k; i < FOUT; i += 64) hs[i] = d_h[row*FOUT + i];
    __syncthreads();
    float a1 = 0.f, a2 = 0.f;
    #pragma unroll 4
    for (int f = 0; f < FOUT; f++) {
        float hv = hs[f];
        a1 += hv * a[f*EOUT + k];
        a2 += hv * a[(FOUT + f)*EOUT + k];
    }
    float c = 0.f;
    #pragma unroll
    for (int f = k; f < FOUT; f += 64) c += hs[f] * fcc_w[f];
    d_ha1[row*EOUT + k] = a1;
    d_ha2[row*EOUT + k] = a2;
    float sv = lrelu(a1 + a2) * fc_w[k];
    red[k] = sv; __syncthreads();
    for (int off = 32; off > 0; off >>= 1) { if (k < off) red[k] += red[k+off]; __syncthreads(); }
    if (k == 0) d_s1[row] = red[0];
    __syncthreads();
    red[k] = c; __syncthreads();
    for (int off = 32; off > 0; off >>= 1) { if (k < off) red[k] += red[k+off]; __syncthreads(); }
    if (k == 0) d_hc[row] = red[0];
}

// ---------------- K3: s2[b,j] ----------------
__global__ void k3_s2(const float* __restrict__ fc_w) {
    int bj = blockIdx.x;           // 2048
    int b = bj / NN, j = bj % NN;
    int k = threadIdx.x;           // 64
    int r1 = (2*j)     & (NN-1);
    int r2 = (2*j + 1) & (NN-1);
    float v = d_ha1[(b*NN + r1)*EOUT + k] + d_ha2[(b*NN + r2)*EOUT + k];
    v = lrelu(v) * fc_w[k];
    __shared__ float red[64];
    red[k] = v; __syncthreads();
    for (int off = 32; off > 0; off >>= 1) { if (k < off) red[k] += red[k+off]; __syncthreads(); }
    if (k == 0) d_s2[bj] = red[0];
}

// ---------------- K4: w_edge proj + mask + softmax + hn ----------------
__global__ void __launch_bounds__(NN) k4_att(
    const float* __restrict__ w_edge, const int* __restrict__ adj,
    const float* __restrict__ wfc_w, const float* __restrict__ wfc_b,
    const float* __restrict__ fc_w, const float* __restrict__ fc_b,
    const float* __restrict__ fcc_b)
{
    int bi = blockIdx.x;           // 2048 = b*NN + i
    int b = bi / NN, i = bi % NN;
    int j = threadIdx.x;           // 128
    __shared__ float wf[BIN*BOUT];
    __shared__ float wb[BOUT], f2[BOUT];
    __shared__ float red[NN];
    for (int t = j; t < BIN*BOUT; t += NN) wf[t] = wfc_w[t];
    if (j < BOUT) { wb[j] = wfc_b[j]; f2[j] = fc_w[BOUT + j]; }
    __syncthreads();

    float we[BIN];
    const float* wp = w_edge + ((size_t)bi*NN + j)*BIN;
    #pragma unroll
    for (int m = 0; m < BIN; m++) we[m] = wp[m];

    float wsum = 0.f;
    #pragma unroll
    for (int k = 0; k < BOUT; k++) {
        float cacc = wb[k];
        #pragma unroll
        for (int m = 0; m < BIN; m++) cacc += we[m] * wf[m*BOUT + k];
        wsum += lrelu(cacc) * f2[k];
    }
    float contrib = (i < 64) ? d_s1[b*NN + 2*i + (j >= 64 ? 1 : 0)]
                             : d_s2[b*NN + j];
    float e = contrib + wsum + fc_b[0];
    int ad = adj[(size_t)bi*NN + j];
    if (ad <= 0) e = -9e15f;

    // softmax over j
    red[j] = e; __syncthreads();
    for (int off = 64; off > 0; off >>= 1) { if (j < off) red[j] = fmaxf(red[j], red[j+off]); __syncthreads(); }
    float mx = red[0]; __syncthreads();
    float ex = expf(e - mx);
    red[j] = ex; __syncthreads();
    for (int off = 64; off > 0; off >>= 1) { if (j < off) red[j] += red[j+off]; __syncthreads(); }
    float att = ex / red[0];

    d_att[(size_t)bi*NN + j] = att;
    d_hn [(size_t)bi*NN + j] = lrelu(att * d_hc[bi] + fcc_b[0]);
}

// ---------------- K5: RNN input pre-projection (both directions) ----------------
__global__ void k5_pre(const float* __restrict__ wih_f, const float* __restrict__ bih_f,
                       const float* __restrict__ bhh_f,
                       const float* __restrict__ wih_b, const float* __restrict__ bih_b,
                       const float* __restrict__ bhh_b)
{
    int bt = blockIdx.x;           // 2048 = b*NN + t (t = step index)
    int b = bt / NN, t = bt % NN;
    int tid = threadIdx.x;         // 128
    __shared__ float xs[2*NN];
    xs[tid]      = d_hn[(b*NN + t)*NN + tid];          // forward input at step t
    xs[NN + tid] = d_hn[(b*NN + (NN-1-t))*NN + tid];   // backward input at step t
    __syncthreads();
    int dir = tid >> 6, c = tid & 63;
    const float* wih = dir ? wih_b : wih_f;
    const float* xr  = xs + dir*NN;
    float acc = dir ? (bih_b[c] + bhh_b[c]) : (bih_f[c] + bhh_f[c]);
    #pragma unroll 4
    for (int q = 0; q < NN; q++) acc += xr[q] * wih[c*NN + q];
    d_pre[dir][(b*NN + t)*CI + c] = acc;
}

// ---------------- K6: serial RNN recurrence ----------------
__global__ void __launch_bounds__(1024) k6_rnn(const float* __restrict__ whh_f,
                                               const float* __restrict__ whh_b)
{
    int dir = blockIdx.x;          // 2 blocks
    int tid = threadIdx.x;         // 1024 = 16 batches x 64 hidden
    int b = tid >> 6, j = tid & 63;
    __shared__ float whh_s[64*65];     // padded to kill bank conflicts
    __shared__ float hs[BB*64];
    const float* whh = dir ? whh_b : whh_f;
    for (int t = tid; t < 64*64; t += 1024) whh_s[(t>>6)*65 + (t & 63)] = whh[t];
    hs[tid] = 0.f;
    __syncthreads();
    const float* pre = d_pre[dir];
    const float* wr = whh_s + j*65;
    for (int t = 0; t < NN; t++) {
        const float* hb = hs + b*64;
        float a0 = 0.f, a1 = 0.f, a2 = 0.f, a3 = 0.f;
        #pragma unroll
        for (int k = 0; k < 64; k += 4) {
            a0 += wr[k]   * hb[k];
            a1 += wr[k+1] * hb[k+1];
            a2 += wr[k+2] * hb[k+2];
            a3 += wr[k+3] * hb[k+3];
        }
        float hnew = tanhf(pre[(b*NN + t)*CI + j] + (a0 + a1) + (a2 + a3));
        __syncthreads();
        hs[b*64 + j] = hnew;
        __syncthreads();
        int tt = dir ? (NN-1-t) : t;
        d_cat[(b*NN + tt)*CATW + dir*CI + j] = lrelu(hnew);
    }
}

// ---------------- K7: h1 = att @ h -> cat[:,128:384] ----------------
__global__ void k7_h1() {
    int bi = blockIdx.x;           // 2048
    int b = bi / NN;
    int f = threadIdx.x;           // 256
    __shared__ float as[NN];
    if (f < NN) as[f] = d_att[(size_t)bi*NN + f];
    __syncthreads();
    float acc = 0.f;
    #pragma unroll 4
    for (int jj = 0; jj < NN; jj++) acc += as[jj] * d_h[(b*NN + jj)*FOUT + f];
    d_cat[bi*CATW + 2*CI + f] = acc;
}

// ---------------- K8: out = elu(cat @ fco_w + fco_b) ----------------
__global__ void k8_out(const float* __restrict__ fco_w, const float* __restrict__ fco_b,
                       float* __restrict__ out)
{
    int row = blockIdx.x;          // 2048
    int c   = threadIdx.x;         // 256
    __shared__ float rs[CATW];
    for (int t = c; t < CATW; t += 256) rs[t] = d_cat[row*CATW + t];
    __syncthreads();
    float acc = fco_b[c];
    #pragma unroll 4
    for (int q = 0; q < CATW; q++) acc += rs[q] * fco_w[q*LL1 + c];
    out[row*LL1 + c] = acc > 0.f ? acc : expm1f(acc);
}

// ---------------- launch ----------------
extern "C" void kernel_launch(void* const* d_in, const int* in_sizes, int n_in,
                              void* d_out, int out_size)
{
    const float* x     = (const float*)d_in[0];
    const int*   adj   = (const int*)  d_in[1];
    const float* wedge = (const float*)d_in[2];
    const float* W     = (const float*)d_in[3];
    const float* a     = (const float*)d_in[4];
    const float* wfc_w = (const float*)d_in[5];
    const float* wfc_b = (const float*)d_in[6];
    const float* fc_w  = (const float*)d_in[7];
    const float* fc_b  = (const float*)d_in[8];
    const float* fcc_w = (const float*)d_in[9];
    const float* fcc_b = (const float*)d_in[10];
    const float* wih_f = (const float*)d_in[11];
    const float* whh_f = (const float*)d_in[12];
    const float* bih_f = (const float*)d_in[13];
    const float* bhh_f = (const float*)d_in[14];
    const float* wih_b = (const float*)d_in[15];
    const float* whh_b = (const float*)d_in[16];
    const float* bih_b = (const float*)d_in[17];
    const float* bhh_b = (const float*)d_in[18];
    const float* fco_w = (const float*)d_in[19];
    const float* fco_b = (const float*)d_in[20];
    float* out = (float*)d_out;

    k1_h  <<<BB*NN, FOUT>>>(x, W);
    k2_ha <<<BB*NN, EOUT>>>(a, fc_w, fcc_w);
    k3_s2 <<<BB*NN, EOUT>>>(fc_w);
    k4_att<<<BB*NN, NN  >>>(wedge, adj, wfc_w, wfc_b, fc_w, fc_b, fcc_b);
    k5_pre<<<BB*NN, NN  >>>(wih_f, bih_f, bhh_f, wih_b, bih_b, bhh_b);
    k7_h1 <<<BB*NN, FOUT>>>();
    k6_rnn<<<2,     1024>>>(whh_f, whh_b);
    k8_out<<<BB*NN, FOUT>>>(fco_w, fco_b, out);
}

// round 2
// speedup vs baseline: 2.9345x; 2.9345x over previous
#include <cuda_runtime.h>
#include <cuda_bf16.h>
#include <math.h>

#define BB   16
#define NN   128
#define FIN  128
#define FOUT 256
#define EOUT 64
#define BIN  14
#define BOUT 64
#define CI   64
#define LL1  256
#define CATW (2*CI + FOUT)   // 384
#define RPB  16              // rows per block for tiled GEMMs

// ---------------- scratch ----------------
__device__ float d_h  [BB*NN*FOUT];       // 2 MB
__device__ float d_ha1[BB*NN*EOUT];
__device__ float d_ha2[BB*NN*EOUT];
__device__ float d_hc [BB*NN];
__device__ float d_s1 [BB*NN];
__device__ float d_s2 [BB*NN];
__device__ float d_att[BB*NN*NN];         // 1 MB
__device__ float d_hn [BB*NN*NN];         // 1 MB
__device__ float d_pre[2][BB*NN*CI];
__device__ float d_cat[BB*NN*CATW];       // 3 MB

__device__ __forceinline__ float lrelu(float v) { return v > 0.f ? v : 0.01f * v; }

// ---------------- K1: h = x @ W   (16 rows / block) ----------------
__global__ void __launch_bounds__(256) k1_h(const float* __restrict__ x,
                                            const float* __restrict__ W) {
    int f    = threadIdx.x;              // 256
    int row0 = blockIdx.x * RPB;         // 128 blocks
    __shared__ __align__(16) float xs[RPB*FIN];
    for (int idx = f; idx < RPB*FIN; idx += 256) xs[idx] = x[row0*FIN + idx];
    __syncthreads();
    float acc[RPB];
    #pragma unroll
    for (int r = 0; r < RPB; r++) acc[r] = 0.f;
    #pragma unroll 4
    for (int kq = 0; kq < FIN/4; kq++) {
        float w0 = W[(4*kq+0)*FOUT + f];
        float w1 = W[(4*kq+1)*FOUT + f];
        float w2 = W[(4*kq+2)*FOUT + f];
        float w3 = W[(4*kq+3)*FOUT + f];
        #pragma unroll
        for (int r = 0; r < RPB; r++) {
            float4 xv = *reinterpret_cast<const float4*>(&xs[r*FIN + 4*kq]);
            acc[r] = fmaf(xv.x, w0, fmaf(xv.y, w1, fmaf(xv.z, w2, fmaf(xv.w, w3, acc[r]))));
        }
    }
    #pragma unroll
    for (int r = 0; r < RPB; r++) d_h[(row0+r)*FOUT + f] = acc[r];
}

// ---------------- K2: ha1/ha2 = h @ a  (16 rows / block) ----------------
__global__ void __launch_bounds__(128) k2_ha(const float* __restrict__ a) {
    int kp   = threadIdx.x;              // 128: 0-63 -> ha1, 64-127 -> ha2
    int row0 = blockIdx.x * RPB;         // 128 blocks
    __shared__ __align__(16) float hs[RPB*FOUT];   // 16 KB
    for (int idx = kp; idx < RPB*FOUT; idx += 128) hs[idx] = d_h[row0*FOUT + idx];
    __syncthreads();
    const float* ap = a + (kp < 64 ? kp : FOUT*EOUT + (kp - 64));
    float acc[RPB];
    #pragma unroll
    for (int r = 0; r < RPB; r++) acc[r] = 0.f;
    #pragma unroll 4
    for (int fq = 0; fq < FOUT/4; fq++) {
        float w0 = ap[(4*fq+0)*EOUT];
        float w1 = ap[(4*fq+1)*EOUT];
        float w2 = ap[(4*fq+2)*EOUT];
        float w3 = ap[(4*fq+3)*EOUT];
        #pragma unroll
        for (int r = 0; r < RPB; r++) {
            float4 hv = *reinterpret_cast<const float4*>(&hs[r*FOUT + 4*fq]);
            acc[r] = fmaf(hv.x, w0, fmaf(hv.y, w1, fmaf(hv.z, w2, fmaf(hv.w, w3, acc[r]))));
        }
    }
    #pragma unroll
    for (int r = 0; r < RPB; r++) {
        int row = row0 + r;
        if (kp < 64) d_ha1[row*EOUT + kp]      = acc[r];
        else         d_ha2[row*EOUT + kp - 64] = acc[r];
    }
}

// ---------------- K3: s1, s2, hc per row ----------------
__global__ void __launch_bounds__(64) k3_red(const float* __restrict__ fc_w,
                                             const float* __restrict__ fcc_w) {
    int row = blockIdx.x;                // 2048
    int b = row >> 7, j = row & 127;
    int t = threadIdx.x;                 // 64
    float hcv = 0.f;
    #pragma unroll
    for (int i = 0; i < 4; i++) hcv += d_h[row*FOUT + t + 64*i] * fcc_w[t + 64*i];
    float fw = fc_w[t];
    float s1v = lrelu(d_ha1[row*EOUT + t] + d_ha2[row*EOUT + t]) * fw;
    int r1 = (2*j) & 127, r2 = (2*j + 1) & 127;
    float s2v = lrelu(d_ha1[(b*NN + r1)*EOUT + t] + d_ha2[(b*NN + r2)*EOUT + t]) * fw;
    #pragma unroll
    for (int off = 16; off > 0; off >>= 1) {
        hcv += __shfl_xor_sync(0xffffffffu, hcv, off);
        s1v += __shfl_xor_sync(0xffffffffu, s1v, off);
        s2v += __shfl_xor_sync(0xffffffffu, s2v, off);
    }
    __shared__ float p[3][2];
    if ((t & 31) == 0) { p[0][t>>5] = hcv; p[1][t>>5] = s1v; p[2][t>>5] = s2v; }
    __syncthreads();
    if (t == 0) {
        d_hc[row] = p[0][0] + p[0][1];
        d_s1[row] = p[1][0] + p[1][1];
        d_s2[row] = p[2][0] + p[2][1];
    }
}

// ---------------- K4: w_edge proj + mask + softmax + hn ----------------
__global__ void __launch_bounds__(NN) k4_att(
    const float* __restrict__ w_edge, const int* __restrict__ adj,
    const float* __restrict__ wfc_w, const float* __restrict__ wfc_b,
    const float* __restrict__ fc_w, const float* __restrict__ fc_b,
    const float* __restrict__ fcc_b)
{
    int bi = blockIdx.x;                 // 2048 = b*NN + i
    int b = bi >> 7, i = bi & 127;
    int j = threadIdx.x;                 // 128
    __shared__ __align__(16) float wf[BIN*BOUT];
    __shared__ __align__(16) float wb[BOUT];
    __shared__ __align__(16) float f2[BOUT];
    for (int t = j; t < BIN*BOUT; t += NN) wf[t] = wfc_w[t];
    if (j < BOUT) { wb[j] = wfc_b[j]; f2[j] = fc_w[BOUT + j]; }
    __syncthreads();

    float we[BIN];
    const float* wp = w_edge + ((size_t)bi*NN + j)*BIN;
    #pragma unroll
    for (int m = 0; m < BIN; m++) we[m] = wp[m];

    const float4* wf4 = reinterpret_cast<const float4*>(wf);
    const float4* wb4 = reinterpret_cast<const float4*>(wb);
    const float4* f24 = reinterpret_cast<const float4*>(f2);
    float wsum = 0.f;
    #pragma unroll 4
    for (int kq = 0; kq < BOUT/4; kq++) {
        float4 acc = wb4[kq];
        #pragma unroll
        for (int m = 0; m < BIN; m++) {
            float4 w4 = wf4[m*(BOUT/4) + kq];
            acc.x = fmaf(we[m], w4.x, acc.x);
            acc.y = fmaf(we[m], w4.y, acc.y);
            acc.z = fmaf(we[m], w4.z, acc.z);
            acc.w = fmaf(we[m], w4.w, acc.w);
        }
        float4 f = f24[kq];
        wsum += lrelu(acc.x)*f.x + lrelu(acc.y)*f.y + lrelu(acc.z)*f.z + lrelu(acc.w)*f.w;
    }

    float contrib = (i < 64) ? d_s1[b*NN + 2*i + (j >= 64 ? 1 : 0)]
                             : d_s2[b*NN + j];
    float e = contrib + wsum + fc_b[0];
    if (adj[(size_t)bi*NN + j] <= 0) e = -9e15f;

    // softmax over j (shuffle + 4-warp combine)
    int lane = j & 31, wid = j >> 5;
    float mx = e;
    #pragma unroll
    for (int off = 16; off > 0; off >>= 1) mx = fmaxf(mx, __shfl_xor_sync(0xffffffffu, mx, off));
    __shared__ float wredm[4], wreds[4];
    if (lane == 0) wredm[wid] = mx;
    __syncthreads();
    mx = fmaxf(fmaxf(wredm[0], wredm[1]), fmaxf(wredm[2], wredm[3]));
    float ex = __expf(e - mx);
    float s = ex;
    #pragma unroll
    for (int off = 16; off > 0; off >>= 1) s += __shfl_xor_sync(0xffffffffu, s, off);
    if (lane == 0) wreds[wid] = s;
    __syncthreads();
    s = (wreds[0] + wreds[1]) + (wreds[2] + wreds[3]);
    float att = ex / s;

    d_att[(size_t)bi*NN + j] = att;
    d_hn [(size_t)bi*NN + j] = lrelu(att * d_hc[bi] + fcc_b[0]);
}

// ---------------- K5: RNN input pre-projection (tiled, smem weights) ----------------
__global__ void __launch_bounds__(64) k5_pre(
    const float* __restrict__ wih_f, const float* __restrict__ bih_f,
    const float* __restrict__ bhh_f,
    const float* __restrict__ wih_b, const float* __restrict__ bih_b,
    const float* __restrict__ bhh_b)
{
    // grid 256: dir = bx/128, b = (bx%128)/8, tile = bx%8
    int bx = blockIdx.x;
    int dir  = bx >> 7;
    int rem  = bx & 127;
    int b    = rem >> 3;
    int t0   = (rem & 7) * RPB;
    int c = threadIdx.x;                 // 64
    __shared__ float wT[NN*65];          // transposed wih, padded: wT[q*65+c]
    __shared__ __align__(16) float xs[RPB*NN];
    const float* wih = dir ? wih_b : wih_f;
    for (int idx = c; idx < CI*NN; idx += 64) {
        int cc = idx >> 7, q = idx & 127;
        wT[q*65 + cc] = wih[idx];
    }
    for (int idx = c; idx < RPB*NN; idx += 64) {
        int r = idx >> 7, q = idx & 127;
        int src = dir ? (NN-1 - (t0+r)) : (t0+r);
        xs[r*NN + q] = d_hn[(b*NN + src)*NN + q];
    }
    __syncthreads();
    float bias = dir ? (bih_b[c] + bhh_b[c]) : (bih_f[c] + bhh_f[c]);
    float acc[RPB];
    #pragma unroll
    for (int r = 0; r < RPB; r++) acc[r] = bias;
    #pragma unroll 4
    for (int qq = 0; qq < NN/4; qq++) {
        float w0 = wT[(4*qq+0)*65 + c];
        float w1 = wT[(4*qq+1)*65 + c];
        float w2 = wT[(4*qq+2)*65 + c];
        float w3 = wT[(4*qq+3)*65 + c];
        #pragma unroll
        for (int r = 0; r < RPB; r++) {
            float4 xv = *reinterpret_cast<const float4*>(&xs[r*NN + 4*qq]);
            acc[r] = fmaf(xv.x, w0, fmaf(xv.y, w1, fmaf(xv.z, w2, fmaf(xv.w, w3, acc[r]))));
        }
    }
    #pragma unroll
    for (int r = 0; r < RPB; r++)
        d_pre[dir][(b*NN + t0 + r)*CI + c] = acc[r];
}

// ---------------- K6: serial RNN recurrence (1 block per (dir, batch)) ----------------
__global__ void __launch_bounds__(64) k6_rnn(const float* __restrict__ whh_f,
                                             const float* __restrict__ whh_b)
{
    int dir = blockIdx.x >> 4;           // 32 blocks
    int b   = blockIdx.x & 15;
    int j   = threadIdx.x;               // 64
    const float* whh = dir ? whh_b : whh_f;
    float w[64];
    #pragma unroll
    for (int k = 0; k < 64; k++) w[k] = whh[j*64 + k];
    __shared__ __align__(16) float hs[64];
    hs[j] = 0.f;
    const float* pre  = d_pre[dir] + (b*NN)*CI + j;
    float*       outp = d_cat + (b*NN)*CATW + dir*CI + j;
    float pv = pre[0];
    __syncthreads();
    for (int t = 0; t < NN; t++) {
        float nv = (t < NN-1) ? pre[(t+1)*CI] : 0.f;   // prefetch next step
        const float4* h4 = reinterpret_cast<const float4*>(hs);
        float a0 = 0.f, a1 = 0.f, a2 = 0.f, a3 = 0.f;
        #pragma unroll
        for (int kk = 0; kk < 16; kk++) {
            float4 hv = h4[kk];
            a0 = fmaf(w[4*kk+0], hv.x, a0);
            a1 = fmaf(w[4*kk+1], hv.y, a1);
            a2 = fmaf(w[4*kk+2], hv.z, a2);
            a3 = fmaf(w[4*kk+3], hv.w, a3);
        }
        float hnew = tanhf(pv + (a0 + a1) + (a2 + a3));
        pv = nv;
        __syncthreads();
        hs[j] = hnew;
        __syncthreads();
        int tt = dir ? (NN-1 - t) : t;
        outp[tt*CATW] = lrelu(hnew);
    }
}

// ---------------- K7: h1 = att @ h  (16 i-rows / block) ----------------
__global__ void __launch_bounds__(256) k7_h1() {
    int bx = blockIdx.x;                 // 128 = b*8 + tile
    int b  = bx >> 3;
    int i0 = (bx & 7) * RPB;
    int f  = threadIdx.x;                // 256
    __shared__ __align__(16) float as[RPB*NN];
    for (int idx = f; idx < RPB*NN; idx += 256)
        as[idx] = d_att[((size_t)b*NN + i0)*NN + idx];
    __syncthreads();
    float acc[RPB];
    #pragma unroll
    for (int r = 0; r < RPB; r++) acc[r] = 0.f;
    const float* hb = d_h + b*NN*FOUT;
    #pragma unroll 4
    for (int jq = 0; jq < NN/4; jq++) {
        float h0 = hb[(4*jq+0)*FOUT + f];
        float h1 = hb[(4*jq+1)*FOUT + f];
        float h2 = hb[(4*jq+2)*FOUT + f];
        float h3 = hb[(4*jq+3)*FOUT + f];
        #pragma unroll
        for (int r = 0; r < RPB; r++) {
            float4 av = *reinterpret_cast<const float4*>(&as[r*NN + 4*jq]);
            acc[r] = fmaf(av.x, h0, fmaf(av.y, h1, fmaf(av.z, h2, fmaf(av.w, h3, acc[r]))));
        }
    }
    #pragma unroll
    for (int r = 0; r < RPB; r++)
        d_cat[(b*NN + i0 + r)*CATW + 2*CI + f] = acc[r];
}

// ---------------- K8: out = elu(cat @ fco_w + fco_b)  (16 rows / block) ----------------
__global__ void __launch_bounds__(256) k8_out(const float* __restrict__ fco_w,
                                              const float* __restrict__ fco_b,
                                              float* __restrict__ out)
{
    int c    = threadIdx.x;              // 256
    int row0 = blockIdx.x * RPB;         // 128 blocks
    __shared__ __align__(16) float cs[RPB*CATW];   // 24 KB
    for (int idx = c; idx < RPB*CATW; idx += 256) cs[idx] = d_cat[row0*CATW + idx];
    __syncthreads();
    float bias = fco_b[c];
    float acc[RPB];
    #pragma unroll
    for (int r = 0; r < RPB; r++) acc[r] = bias;
    #pragma unroll 4
    for (int qq = 0; qq < CATW/4; qq++) {
        float w0 = fco_w[(4*qq+0)*LL1 + c];
        float w1 = fco_w[(4*qq+1)*LL1 + c];
        float w2 = fco_w[(4*qq+2)*LL1 + c];
        float w3 = fco_w[(4*qq+3)*LL1 + c];
        #pragma unroll
        for (int r = 0; r < RPB; r++) {
            float4 cv = *reinterpret_cast<const float4*>(&cs[r*CATW + 4*qq]);
            acc[r] = fmaf(cv.x, w0, fmaf(cv.y, w1, fmaf(cv.z, w2, fmaf(cv.w, w3, acc[r]))));
        }
    }
    #pragma unroll
    for (int r = 0; r < RPB; r++) {
        float v = acc[r];
        out[(row0+r)*LL1 + c] = v > 0.f ? v : expm1f(v);
    }
}

// ---------------- launch ----------------
extern "C" void kernel_launch(void* const* d_in, const int* in_sizes, int n_in,
                              void* d_out, int out_size)
{
    const float* x     = (const float*)d_in[0];
    const int*   adj   = (const int*)  d_in[1];
    const float* wedge = (const float*)d_in[2];
    const float* W     = (const float*)d_in[3];
    const float* a     = (const float*)d_in[4];
    const float* wfc_w = (const float*)d_in[5];
    const float* wfc_b = (const float*)d_in[6];
    const float* fc_w  = (const float*)d_in[7];
    const float* fc_b  = (const float*)d_in[8];
    const float* fcc_w = (const float*)d_in[9];
    const float* fcc_b = (const float*)d_in[10];
    const float* wih_f = (const float*)d_in[11];
    const float* whh_f = (const float*)d_in[12];
    const float* bih_f = (const float*)d_in[13];
    const float* bhh_f = (const float*)d_in[14];
    const float* wih_b = (const float*)d_in[15];
    const float* whh_b = (const float*)d_in[16];
    const float* bih_b = (const float*)d_in[17];
    const float* bhh_b = (const float*)d_in[18];
    const float* fco_w = (const float*)d_in[19];
    const float* fco_b = (const float*)d_in[20];
    float* out = (float*)d_out;

    k1_h  <<<BB*NN/RPB, 256>>>(x, W);
    k2_ha <<<BB*NN/RPB, 128>>>(a);
    k3_red<<<BB*NN,      64>>>(fc_w, fcc_w);
    k4_att<<<BB*NN,      NN>>>(wedge, adj, wfc_w, wfc_b, fc_w, fc_b, fcc_b);
    k5_pre<<<2*BB*NN/(RPB*NN)*NN, 64>>>(wih_f, bih_f, bhh_f, wih_b, bih_b, bhh_b); // 256 blocks
    k7_h1 <<<BB*NN/RPB, 256>>>();
    k6_rnn<<<2*BB,       64>>>(whh_f, whh_b);
    k8_out<<<BB*NN/RPB, 256>>>(fco_w, fco_b, out);
}

// round 3
// speedup vs baseline: 3.4660x; 1.1811x over previous
#include <cuda_runtime.h>
#include <cuda_bf16.h>
#include <math.h>

#define BB   16
#define NN   128
#define FIN  128
#define FOUT 256
#define EOUT 64
#define BIN  14
#define BOUT 64
#define CI   64
#define LL1  256
#define CATW (2*CI + FOUT)   // 384
#define RPB  16

typedef unsigned long long ull;

// ---------------- scratch ----------------
__device__ float d_h  [BB*NN*FOUT];
__device__ float d_ha1[BB*NN*EOUT];
__device__ float d_ha2[BB*NN*EOUT];
__device__ float d_hc [BB*NN];
__device__ float d_s1 [BB*NN];
__device__ float d_s2 [BB*NN];
__device__ float d_att[BB*NN*NN];
__device__ float d_hn [BB*NN*NN];
__device__ float d_pre[2][BB*NN*CI];
__device__ float d_cat[BB*NN*CATW];

__device__ __forceinline__ float lrelu(float v) { return v > 0.f ? v : 0.01f * v; }

// ---- packed fp32x2 helpers ----
__device__ __forceinline__ ull pk(float lo, float hi) {
    ull r; asm("mov.b64 %0, {%1,%2};" : "=l"(r) : "f"(lo), "f"(hi)); return r;
}
__device__ __forceinline__ void fma2(ull& d, ull a, ull b) {
    asm("fma.rn.f32x2 %0, %1, %2, %3;" : "=l"(d) : "l"(a), "l"(b), "l"(d));
}
__device__ __forceinline__ ull add2(ull a, ull b) {
    ull r; asm("add.rn.f32x2 %0, %1, %2;" : "=l"(r) : "l"(a), "l"(b)); return r;
}
__device__ __forceinline__ float2 upk(ull v) {
    float2 f; asm("mov.b64 {%0,%1}, %2;" : "=f"(f.x), "=f"(f.y) : "l"(v)); return f;
}
__device__ __forceinline__ float hsum2(ull v) { float2 p = upk(v); return p.x + p.y; }

// ---------------- KA: h = x@W  then  ha1/ha2 = h@a   (fused, 16 rows/block) --------
__global__ void __launch_bounds__(256) kA(const float* __restrict__ x,
                                          const float* __restrict__ W,
                                          const float* __restrict__ a) {
    int f    = threadIdx.x;
    int row0 = blockIdx.x * RPB;
    __shared__ __align__(16) float xs[RPB*FIN];   // 8 KB
    __shared__ __align__(16) float hs[RPB*FOUT];  // 16 KB
    {
        const float4* src = reinterpret_cast<const float4*>(x + row0*FIN);
        float4* dst = reinterpret_cast<float4*>(xs);
        for (int t = f; t < RPB*FIN/4; t += 256) dst[t] = src[t];
    }
    __syncthreads();
    // ---- k1: h = x @ W, packed over k pairs ----
    {
        ull acc[RPB];
        #pragma unroll
        for (int r = 0; r < RPB; r++) acc[r] = 0ull;
        #pragma unroll 2
        for (int kq = 0; kq < FIN/4; kq++) {
            float w0 = W[(4*kq+0)*FOUT + f];
            float w1 = W[(4*kq+1)*FOUT + f];
            float w2 = W[(4*kq+2)*FOUT + f];
            float w3 = W[(4*kq+3)*FOUT + f];
            ull wp0 = pk(w0, w1), wp1 = pk(w2, w3);
            #pragma unroll
            for (int r = 0; r < RPB; r++) {
                ulonglong2 xv = *reinterpret_cast<const ulonglong2*>(&xs[r*FIN + 4*kq]);
                fma2(acc[r], xv.x, wp0);
                fma2(acc[r], xv.y, wp1);
            }
        }
        #pragma unroll
        for (int r = 0; r < RPB; r++) {
            float v = hsum2(acc[r]);
            hs[r*FOUT + f] = v;
            d_h[(row0+r)*FOUT + f] = v;
        }
    }
    __syncthreads();
    // ---- k2: ha1/ha2, 4 groups of 64 threads, 8 rows each ----
    {
        int g  = f >> 6;          // 0..3
        int kp = f & 63;
        int half = g >> 1;        // 0 -> ha1, 1 -> ha2
        int r0 = (g & 1) * 8;
        const float* ap = a + half*FOUT*EOUT + kp;
        ull acc[8];
        #pragma unroll
        for (int r = 0; r < 8; r++) acc[r] = 0ull;
        #pragma unroll 2
        for (int fq = 0; fq < FOUT/4; fq++) {
            float w0 = ap[(4*fq+0)*EOUT];
            float w1 = ap[(4*fq+1)*EOUT];
            float w2 = ap[(4*fq+2)*EOUT];
            float w3 = ap[(4*fq+3)*EOUT];
            ull wp0 = pk(w0, w1), wp1 = pk(w2, w3);
            #pragma unroll
            for (int r = 0; r < 8; r++) {
                ulonglong2 hv = *reinterpret_cast<const ulonglong2*>(&hs[(r0+r)*FOUT + 4*fq]);
                fma2(acc[r], hv.x, wp0);
                fma2(acc[r], hv.y, wp1);
            }
        }
        float* dst = half ? d_ha2 : d_ha1;
        #pragma unroll
        for (int r = 0; r < 8; r++)
            dst[(row0 + r0 + r)*EOUT + kp] = hsum2(acc[r]);
    }
}

// ---------------- K3: s1, s2, hc per row ----------------
__global__ void __launch_bounds__(64) k3_red(const float* __restrict__ fc_w,
                                             const float* __restrict__ fcc_w) {
    int row = blockIdx.x;
    int b = row >> 7, j = row & 127;
    int t = threadIdx.x;
    float hcv = 0.f;
    #pragma unroll
    for (int i = 0; i < 4; i++) hcv += d_h[row*FOUT + t + 64*i] * fcc_w[t + 64*i];
    float fw = fc_w[t];
    float s1v = lrelu(d_ha1[row*EOUT + t] + d_ha2[row*EOUT + t]) * fw;
    int r1 = (2*j) & 127, r2 = (2*j + 1) & 127;
    float s2v = lrelu(d_ha1[(b*NN + r1)*EOUT + t] + d_ha2[(b*NN + r2)*EOUT + t]) * fw;
    #pragma unroll
    for (int off = 16; off > 0; off >>= 1) {
        hcv += __shfl_xor_sync(0xffffffffu, hcv, off);
        s1v += __shfl_xor_sync(0xffffffffu, s1v, off);
        s2v += __shfl_xor_sync(0xffffffffu, s2v, off);
    }
    __shared__ float p[3][2];
    if ((t & 31) == 0) { p[0][t>>5] = hcv; p[1][t>>5] = s1v; p[2][t>>5] = s2v; }
    __syncthreads();
    if (t == 0) {
        d_hc[row] = p[0][0] + p[0][1];
        d_s1[row] = p[1][0] + p[1][1];
        d_s2[row] = p[2][0] + p[2][1];
    }
}

// ---------------- K4: w_edge proj + mask + softmax + hn (smem-staged, packed) ------
__global__ void __launch_bounds__(NN) k4_att(
    const float* __restrict__ w_edge, const int* __restrict__ adj,
    const float* __restrict__ wfc_w, const float* __restrict__ wfc_b,
    const float* __restrict__ fc_w, const float* __restrict__ fc_b,
    const float* __restrict__ fcc_b)
{
    int bi = blockIdx.x;
    int b = bi >> 7, i = bi & 127;
    int j = threadIdx.x;
    __shared__ __align__(16) float wes[NN*BIN];     // 7 KB: staged w_edge row
    __shared__ __align__(16) float wf[BIN*BOUT];
    __shared__ __align__(16) float wb[BOUT];
    __shared__ __align__(16) float f2[BOUT];
    {
        const float4* src = reinterpret_cast<const float4*>(w_edge + (size_t)bi*NN*BIN);
        float4* dst = reinterpret_cast<float4*>(wes);
        for (int t = j; t < NN*BIN/4; t += NN) dst[t] = src[t];
    }
    for (int t = j; t < BIN*BOUT; t += NN) wf[t] = wfc_w[t];
    if (j < BOUT) { wb[j] = wfc_b[j]; f2[j] = fc_w[BOUT + j]; }
    __syncthreads();

    ull we2[BIN];
    #pragma unroll
    for (int m = 0; m < BIN; m++) { float w = wes[j*BIN + m]; we2[m] = pk(w, w); }

    const ulonglong2* wfp = reinterpret_cast<const ulonglong2*>(wf);  // [m][16]
    const ulonglong2* wbp = reinterpret_cast<const ulonglong2*>(wb);
    const float4*     f2p = reinterpret_cast<const float4*>(f2);
    float wsum = 0.f;
    #pragma unroll 4
    for (int kq = 0; kq < BOUT/4; kq++) {
        ulonglong2 aq = wbp[kq];
        ull a0 = aq.x, a1 = aq.y;
        #pragma unroll
        for (int m = 0; m < BIN; m++) {
            ulonglong2 w2 = wfp[m*16 + kq];
            fma2(a0, we2[m], w2.x);
            fma2(a1, we2[m], w2.y);
        }
        float2 p0 = upk(a0), p1 = upk(a1);
        float4 fv = f2p[kq];
        wsum += lrelu(p0.x)*fv.x + lrelu(p0.y)*fv.y + lrelu(p1.x)*fv.z + lrelu(p1.y)*fv.w;
    }

    float contrib = (i < 64) ? d_s1[b*NN + 2*i + (j >= 64 ? 1 : 0)]
                             : d_s2[b*NN + j];
    float e = contrib + wsum + fc_b[0];
    if (adj[(size_t)bi*NN + j] <= 0) e = -9e15f;

    int lane = j & 31, wid = j >> 5;
    float mx = e;
    #pragma unroll
    for (int off = 16; off > 0; off >>= 1) mx = fmaxf(mx, __shfl_xor_sync(0xffffffffu, mx, off));
    __shared__ float wredm[4], wreds[4];
    if (lane == 0) wredm[wid] = mx;
    __syncthreads();
    mx = fmaxf(fmaxf(wredm[0], wredm[1]), fmaxf(wredm[2], wredm[3]));
    float ex = __expf(e - mx);
    float s = ex;
    #pragma unroll
    for (int off = 16; off > 0; off >>= 1) s += __shfl_xor_sync(0xffffffffu, s, off);
    if (lane == 0) wreds[wid] = s;
    __syncthreads();
    s = (wreds[0] + wreds[1]) + (wreds[2] + wreds[3]);
    float att = ex / s;

    d_att[(size_t)bi*NN + j] = att;
    d_hn [(size_t)bi*NN + j] = lrelu(att * d_hc[bi] + fcc_b[0]);
}

// ---------------- KB: k7 (h1 = att@h) and k5 (RNN pre-proj), grid-branched ---------
__global__ void __launch_bounds__(256) kB(
    const float* __restrict__ wih_f, const float* __restrict__ bih_f,
    const float* __restrict__ bhh_f,
    const float* __restrict__ wih_b, const float* __restrict__ bih_b,
    const float* __restrict__ bhh_b)
{
    __shared__ __align__(16) float pool[NN*65 + RPB*NN];  // 41.5 KB
    int tid = threadIdx.x;
    if (blockIdx.x < 128) {
        // ---- k7: h1 = att @ h, 16 i-rows per block ----
        int bx = blockIdx.x;
        int b  = bx >> 3;
        int i0 = (bx & 7) * RPB;
        float* as = pool;          // RPB*NN
        for (int idx = tid; idx < RPB*NN; idx += 256)
            as[idx] = d_att[((size_t)b*NN + i0)*NN + idx];
        __syncthreads();
        ull acc[RPB];
        #pragma unroll
        for (int r = 0; r < RPB; r++) acc[r] = 0ull;
        const float* hb = d_h + b*NN*FOUT;
        #pragma unroll 2
        for (int jq = 0; jq < NN/4; jq++) {
            float h0 = hb[(4*jq+0)*FOUT + tid];
            float h1 = hb[(4*jq+1)*FOUT + tid];
            float h2 = hb[(4*jq+2)*FOUT + tid];
            float h3 = hb[(4*jq+3)*FOUT + tid];
            ull hp0 = pk(h0, h1), hp1 = pk(h2, h3);
            #pragma unroll
            for (int r = 0; r < RPB; r++) {
                ulonglong2 av = *reinterpret_cast<const ulonglong2*>(&as[r*NN + 4*jq]);
                fma2(acc[r], av.x, hp0);
                fma2(acc[r], av.y, hp1);
            }
        }
        #pragma unroll
        for (int r = 0; r < RPB; r++)
            d_cat[(b*NN + i0 + r)*CATW + 2*CI + tid] = hsum2(acc[r]);
    } else {
        // ---- k5: pre[dir][b,t,c], 16 t-rows per block, 256 threads ----
        int bx2 = blockIdx.x - 128;         // 0..255
        int dir = bx2 >> 7;
        int rem = bx2 & 127;
        int b   = rem >> 3;
        int t0  = (rem & 7) * RPB;
        int c    = tid & 63;
        int quad = tid >> 6;                // 4 rows each
        float* wT = pool;                   // NN*65
        float* xs = pool + NN*65;           // RPB*NN
        const float* wih = dir ? wih_b : wih_f;
        for (int idx = tid; idx < CI*NN; idx += 256) {
            int cc = idx >> 7, q = idx & 127;
            wT[q*65 + cc] = wih[idx];
        }
        for (int idx = tid; idx < RPB*NN; idx += 256) {
            int r = idx >> 7, q = idx & 127;
            int src = dir ? (NN-1 - (t0+r)) : (t0+r);
            xs[r*NN + q] = d_hn[(b*NN + src)*NN + q];
        }
        __syncthreads();
        float bias = dir ? (bih_b[c] + bhh_b[c]) : (bih_f[c] + bhh_f[c]);
        float acc[4];
        #pragma unroll
        for (int r = 0; r < 4; r++) acc[r] = bias;
        #pragma unroll 2
        for (int qq = 0; qq < NN/4; qq++) {
            float w0 = wT[(4*qq+0)*65 + c];
            float w1 = wT[(4*qq+1)*65 + c];
            float w2 = wT[(4*qq+2)*65 + c];
            float w3 = wT[(4*qq+3)*65 + c];
            #pragma unroll
            for (int r = 0; r < 4; r++) {
                float4 xv = *reinterpret_cast<const float4*>(&xs[(quad*4+r)*NN + 4*qq]);
                acc[r] = fmaf(xv.x, w0, fmaf(xv.y, w1, fmaf(xv.z, w2, fmaf(xv.w, w3, acc[r]))));
            }
        }
        #pragma unroll
        for (int r = 0; r < 4; r++)
            d_pre[dir][(b*NN + t0 + quad*4 + r)*CI + c] = acc[r];
    }
}

// ---------------- K6: serial RNN recurrence ----------------
__global__ void __launch_bounds__(64) k6_rnn(const float* __restrict__ whh_f,
                                             const float* __restrict__ whh_b)
{
    int dir = blockIdx.x >> 4;
    int b   = blockIdx.x & 15;
    int j   = threadIdx.x;
    const float* whh = dir ? whh_b : whh_f;
    ull w2[32];
    {
        const float4* wr = reinterpret_cast<const float4*>(whh + j*64);
        #pragma unroll
        for (int kk = 0; kk < 16; kk++) {
            float4 wv = wr[kk];
            w2[2*kk]   = pk(wv.x, wv.y);
            w2[2*kk+1] = pk(wv.z, wv.w);
        }
    }
    __shared__ __align__(16) float hbuf[2][64];
    hbuf[0][j] = 0.f;
    const float* pre  = d_pre[dir] + (b*NN)*CI + j;
    float*       outp = d_cat + (b*NN)*CATW + dir*CI + j;
    float pv = pre[0];
    __syncthreads();
    #pragma unroll 1
    for (int t = 0; t < NN; t++) {
        int cur = t & 1;
        float nv = (t < NN-1) ? pre[(t+1)*CI] : 0.f;
        const ulonglong2* h4 = reinterpret_cast<const ulonglong2*>(hbuf[cur]);
        ull a0 = 0ull, a1 = 0ull, a2 = 0ull, a3 = 0ull;
        #pragma unroll
        for (int kk = 0; kk < 16; kk++) {
            ulonglong2 hv = h4[kk];
            ull& acc = (kk & 3) == 0 ? a0 : ((kk & 3) == 1 ? a1 : ((kk & 3) == 2 ? a2 : a3));
            fma2(acc, w2[2*kk],   hv.x);
            fma2(acc, w2[2*kk+1], hv.y);
        }
        float dot = hsum2(add2(add2(a0, a1), add2(a2, a3)));
        float sarg = pv + dot;
        // tanh(x) = 1 - 2/(exp(2x)+1)
        float ee = __expf(2.f * sarg);
        float th = 1.f - __fdividef(2.f, ee + 1.f);
        pv = nv;
        hbuf[cur ^ 1][j] = th;
        __syncthreads();
        int tt = dir ? (NN-1 - t) : t;
        outp[tt*CATW] = lrelu(th);
    }
}

// ---------------- K8: out = elu(cat @ fco_w + fco_b), packed ----------------
__global__ void __launch_bounds__(256) k8_out(const float* __restrict__ fco_w,
                                              const float* __restrict__ fco_b,
                                              float* __restrict__ out)
{
    int c    = threadIdx.x;
    int row0 = blockIdx.x * RPB;
    __shared__ __align__(16) float cs[RPB*CATW];  // 24 KB
    {
        const float4* src = reinterpret_cast<const float4*>(d_cat + row0*CATW);
        float4* dst = reinterpret_cast<float4*>(cs);
        for (int t = c; t < RPB*CATW/4; t += 256) dst[t] = src[t];
    }
    __syncthreads();
    float bias = fco_b[c];
    ull acc[RPB];
    #pragma unroll
    for (int r = 0; r < RPB; r++) acc[r] = 0ull;
    #pragma unroll 2
    for (int qq = 0; qq < CATW/4; qq++) {
        float w0 = fco_w[(4*qq+0)*LL1 + c];
        float w1 = fco_w[(4*qq+1)*LL1 + c];
        float w2 = fco_w[(4*qq+2)*LL1 + c];
        float w3 = fco_w[(4*qq+3)*LL1 + c];
        ull wp0 = pk(w0, w1), wp1 = pk(w2, w3);
        #pragma unroll
        for (int r = 0; r < RPB; r++) {
            ulonglong2 cv = *reinterpret_cast<const ulonglong2*>(&cs[r*CATW + 4*qq]);
            fma2(acc[r], cv.x, wp0);
            fma2(acc[r], cv.y, wp1);
        }
    }
    #pragma unroll
    for (int r = 0; r < RPB; r++) {
        float v = hsum2(acc[r]) + bias;
        out[(row0+r)*LL1 + c] = v > 0.f ? v : expm1f(v);
    }
}

// ---------------- launch ----------------
extern "C" void kernel_launch(void* const* d_in, const int* in_sizes, int n_in,
                              void* d_out, int out_size)
{
    const float* x     = (const float*)d_in[0];
    const int*   adj   = (const int*)  d_in[1];
    const float* wedge = (const float*)d_in[2];
    const float* W     = (const float*)d_in[3];
    const float* a     = (const float*)d_in[4];
    const float* wfc_w = (const float*)d_in[5];
    const float* wfc_b = (const float*)d_in[6];
    const float* fc_w  = (const float*)d_in[7];
    const float* fc_b  = (const float*)d_in[8];
    const float* fcc_w = (const float*)d_in[9];
    const float* fcc_b = (const float*)d_in[10];
    const float* wih_f = (const float*)d_in[11];
    const float* whh_f = (const float*)d_in[12];
    const float* bih_f = (const float*)d_in[13];
    const float* bhh_f = (const float*)d_in[14];
    const float* wih_b = (const float*)d_in[15];
    const float* whh_b = (const float*)d_in[16];
    const float* bih_b = (const float*)d_in[17];
    const float* bhh_b = (const float*)d_in[18];
    const float* fco_w = (const float*)d_in[19];
    const float* fco_b = (const float*)d_in[20];
    float* out = (float*)d_out;

    kA    <<<BB*NN/RPB, 256>>>(x, W, a);
    k3_red<<<BB*NN,      64>>>(fc_w, fcc_w);
    k4_att<<<BB*NN,      NN>>>(wedge, adj, wfc_w, wfc_b, fc_w, fc_b, fcc_b);
    kB    <<<384,       256>>>(wih_f, bih_f, bhh_f, wih_b, bih_b, bhh_b);
    k6_rnn<<<2*BB,       64>>>(whh_f, whh_b);
    k8_out<<<BB*NN/RPB, 256>>>(fco_w, fco_b, out);
}

// round 4
// speedup vs baseline: 3.7646x; 1.0862x over previous
#include <cuda_runtime.h>
#include <cuda_bf16.h>
#include <math.h>

#define BB   16
#define NN   128
#define FIN  128
#define FOUT 256
#define EOUT 64
#define BIN  14
#define BOUT 64
#define CI   64
#define LL1  256
#define CATW (2*CI + FOUT)   // 384
#define RPB  16

typedef unsigned long long ull;

// ---------------- scratch ----------------
__device__ float d_h  [BB*NN*FOUT];
__device__ float d_ha1[BB*NN*EOUT];
__device__ float d_ha2[BB*NN*EOUT];
__device__ float d_hc [BB*NN];
__device__ float d_s1 [BB*NN];
__device__ float d_s2 [BB*NN];
__device__ float d_ee [BB*NN*NN];
__device__ float d_att[BB*NN*NN];
__device__ float d_hn [BB*NN*NN];
__device__ float d_pre[2][BB*NN*CI];
__device__ float d_cat[BB*NN*CATW];

__device__ __forceinline__ float lrelu(float v) { return v > 0.f ? v : 0.01f * v; }

// ---- packed fp32x2 helpers ----
__device__ __forceinline__ ull pk(float lo, float hi) {
    ull r; asm("mov.b64 %0, {%1,%2};" : "=l"(r) : "f"(lo), "f"(hi)); return r;
}
__device__ __forceinline__ void fma2(ull& d, ull a, ull b) {
    asm("fma.rn.f32x2 %0, %1, %2, %3;" : "=l"(d) : "l"(a), "l"(b), "l"(d));
}
__device__ __forceinline__ ull add2(ull a, ull b) {
    ull r; asm("add.rn.f32x2 %0, %1, %2;" : "=l"(r) : "l"(a), "l"(b)); return r;
}
__device__ __forceinline__ float2 upk(ull v) {
    float2 f; asm("mov.b64 {%0,%1}, %2;" : "=f"(f.x), "=f"(f.y) : "l"(v)); return f;
}
__device__ __forceinline__ float hsum2(ull v) { float2 p = upk(v); return p.x + p.y; }

// ============ K1: blocks [0,128): h = x@W, ha = h@a ; blocks [128,1152): wsum ======
__global__ void __launch_bounds__(256) K1(const float* __restrict__ x,
                                          const float* __restrict__ W,
                                          const float* __restrict__ a,
                                          const float* __restrict__ w_edge,
                                          const float* __restrict__ wfc_w,
                                          const float* __restrict__ wfc_b,
                                          const float* __restrict__ fc_w) {
    __shared__ __align__(16) float smem_u[RPB*FIN + RPB*FOUT];   // 24 KB
    int tid = threadIdx.x;
    if (blockIdx.x < 128) {
        // ---------- kA ----------
        int f    = tid;
        int row0 = blockIdx.x * RPB;
        float* xs = smem_u;               // RPB*FIN
        float* hs = smem_u + RPB*FIN;     // RPB*FOUT
        {
            const float4* src = reinterpret_cast<const float4*>(x + row0*FIN);
            float4* dst = reinterpret_cast<float4*>(xs);
            for (int t = f; t < RPB*FIN/4; t += 256) dst[t] = src[t];
        }
        __syncthreads();
        {
            ull acc[RPB];
            #pragma unroll
            for (int r = 0; r < RPB; r++) acc[r] = 0ull;
            #pragma unroll 2
            for (int kq = 0; kq < FIN/4; kq++) {
                float w0 = W[(4*kq+0)*FOUT + f];
                float w1 = W[(4*kq+1)*FOUT + f];
                float w2 = W[(4*kq+2)*FOUT + f];
                float w3 = W[(4*kq+3)*FOUT + f];
                ull wp0 = pk(w0, w1), wp1 = pk(w2, w3);
                #pragma unroll
                for (int r = 0; r < RPB; r++) {
                    ulonglong2 xv = *reinterpret_cast<const ulonglong2*>(&xs[r*FIN + 4*kq]);
                    fma2(acc[r], xv.x, wp0);
                    fma2(acc[r], xv.y, wp1);
                }
            }
            #pragma unroll
            for (int r = 0; r < RPB; r++) {
                float v = hsum2(acc[r]);
                hs[r*FOUT + f] = v;
                d_h[(row0+r)*FOUT + f] = v;
            }
        }
        __syncthreads();
        {
            int g  = f >> 6;
            int kp = f & 63;
            int half = g >> 1;
            int r0 = (g & 1) * 8;
            const float* ap = a + half*FOUT*EOUT + kp;
            ull acc[8];
            #pragma unroll
            for (int r = 0; r < 8; r++) acc[r] = 0ull;
            #pragma unroll 2
            for (int fq = 0; fq < FOUT/4; fq++) {
                float w0 = ap[(4*fq+0)*EOUT];
                float w1 = ap[(4*fq+1)*EOUT];
                float w2 = ap[(4*fq+2)*EOUT];
                float w3 = ap[(4*fq+3)*EOUT];
                ull wp0 = pk(w0, w1), wp1 = pk(w2, w3);
                #pragma unroll
                for (int r = 0; r < 8; r++) {
                    ulonglong2 hv = *reinterpret_cast<const ulonglong2*>(&hs[(r0+r)*FOUT + 4*fq]);
                    fma2(acc[r], hv.x, wp0);
                    fma2(acc[r], hv.y, wp1);
                }
            }
            float* dst = half ? d_ha2 : d_ha1;
            #pragma unroll
            for (int r = 0; r < 8; r++)
                dst[(row0 + r0 + r)*EOUT + kp] = hsum2(acc[r]);
        }
    } else {
        // ---------- wsum: 2 (b,i) rows per block ----------
        int w    = blockIdx.x - 128;      // 0..1023
        int row0 = w * 2;
        float* wes = smem_u;                       // 2*NN*BIN = 3584 floats
        float* wf  = smem_u + 2*NN*BIN;            // 896
        float* wb  = wf + BIN*BOUT;                // 64
        float* f2  = wb + BOUT;                    // 64
        {
            const float4* src = reinterpret_cast<const float4*>(w_edge + (size_t)row0*NN*BIN);
            float4* dst = reinterpret_cast<float4*>(wes);
            for (int t = tid; t < 2*NN*BIN/4; t += 256) dst[t] = src[t];
        }
        for (int t = tid; t < BIN*BOUT; t += 256) wf[t] = wfc_w[t];
        if (tid < BOUT) { wb[tid] = wfc_b[tid]; f2[tid] = fc_w[BOUT + tid]; }
        __syncthreads();

        int r = tid >> 7, j = tid & 127;
        ull we2[BIN];
        #pragma unroll
        for (int m = 0; m < BIN; m++) { float v = wes[(r*NN + j)*BIN + m]; we2[m] = pk(v, v); }

        const ulonglong2* wfp = reinterpret_cast<const ulonglong2*>(wf);
        const ulonglong2* wbp = reinterpret_cast<const ulonglong2*>(wb);
        const float4*     f2p = reinterpret_cast<const float4*>(f2);
        float wsum = 0.f;
        #pragma unroll 4
        for (int kq = 0; kq < BOUT/4; kq++) {
            ulonglong2 aq = wbp[kq];
            ull a0 = aq.x, a1 = aq.y;
            #pragma unroll
            for (int m = 0; m < BIN; m++) {
                ulonglong2 w2 = wfp[m*16 + kq];
                fma2(a0, we2[m], w2.x);
                fma2(a1, we2[m], w2.y);
            }
            float2 p0 = upk(a0), p1 = upk(a1);
            float4 fv = f2p[kq];
            wsum += lrelu(p0.x)*fv.x + lrelu(p0.y)*fv.y + lrelu(p1.x)*fv.z + lrelu(p1.y)*fv.w;
        }
        d_ee[(row0 + r)*NN + j] = wsum;
    }
}

// ---------------- K3: s1, s2, hc per row ----------------
__global__ void __launch_bounds__(64) k3_red(const float* __restrict__ fc_w,
                                             const float* __restrict__ fcc_w) {
    int row = blockIdx.x;
    int b = row >> 7, j = row & 127;
    int t = threadIdx.x;
    float hcv = 0.f;
    #pragma unroll
    for (int i = 0; i < 4; i++) hcv += d_h[row*FOUT + t + 64*i] * fcc_w[t + 64*i];
    float fw = fc_w[t];
    float s1v = lrelu(d_ha1[row*EOUT + t] + d_ha2[row*EOUT + t]) * fw;
    int r1 = (2*j) & 127, r2 = (2*j + 1) & 127;
    float s2v = lrelu(d_ha1[(b*NN + r1)*EOUT + t] + d_ha2[(b*NN + r2)*EOUT + t]) * fw;
    #pragma unroll
    for (int off = 16; off > 0; off >>= 1) {
        hcv += __shfl_xor_sync(0xffffffffu, hcv, off);
        s1v += __shfl_xor_sync(0xffffffffu, s1v, off);
        s2v += __shfl_xor_sync(0xffffffffu, s2v, off);
    }
    __shared__ float p[3][2];
    if ((t & 31) == 0) { p[0][t>>5] = hcv; p[1][t>>5] = s1v; p[2][t>>5] = s2v; }
    __syncthreads();
    if (t == 0) {
        d_hc[row] = p[0][0] + p[0][1];
        d_s1[row] = p[1][0] + p[1][1];
        d_s2[row] = p[2][0] + p[2][1];
    }
}

// ---------------- K4b: mask + softmax + hn ----------------
__global__ void __launch_bounds__(NN) k4b(const int* __restrict__ adj,
                                          const float* __restrict__ fc_b,
                                          const float* __restrict__ fcc_b)
{
    int bi = blockIdx.x;
    int b = bi >> 7, i = bi & 127;
    int j = threadIdx.x;
    float contrib = (i < 64) ? d_s1[b*NN + 2*i + (j >= 64 ? 1 : 0)]
                             : d_s2[b*NN + j];
    float e = d_ee[(size_t)bi*NN + j] + contrib + fc_b[0];
    if (adj[(size_t)bi*NN + j] <= 0) e = -9e15f;

    int lane = j & 31, wid = j >> 5;
    float mx = e;
    #pragma unroll
    for (int off = 16; off > 0; off >>= 1) mx = fmaxf(mx, __shfl_xor_sync(0xffffffffu, mx, off));
    __shared__ float wredm[4], wreds[4];
    if (lane == 0) wredm[wid] = mx;
    __syncthreads();
    mx = fmaxf(fmaxf(wredm[0], wredm[1]), fmaxf(wredm[2], wredm[3]));
    float ex = __expf(e - mx);
    float s = ex;
    #pragma unroll
    for (int off = 16; off > 0; off >>= 1) s += __shfl_xor_sync(0xffffffffu, s, off);
    if (lane == 0) wreds[wid] = s;
    __syncthreads();
    s = (wreds[0] + wreds[1]) + (wreds[2] + wreds[3]);
    float att = ex / s;

    d_att[(size_t)bi*NN + j] = att;
    d_hn [(size_t)bi*NN + j] = lrelu(att * d_hc[bi] + fcc_b[0]);
}

// ---------------- KB: blocks [0,256): h1 = att@h (8 rows); [256,512): RNN pre ------
__global__ void __launch_bounds__(256) kB(
    const float* __restrict__ wih_f, const float* __restrict__ bih_f,
    const float* __restrict__ bhh_f,
    const float* __restrict__ wih_b, const float* __restrict__ bih_b,
    const float* __restrict__ bhh_b)
{
    __shared__ __align__(16) float pool[NN*65 + RPB*NN];
    int tid = threadIdx.x;
    if (blockIdx.x < 256) {
        // ---- k7: h1 = att @ h, 8 i-rows per block ----
        int bx = blockIdx.x;
        int b  = bx >> 4;
        int i0 = (bx & 15) * 8;
        float* as = pool;          // 8*NN
        for (int idx = tid; idx < 8*NN; idx += 256)
            as[idx] = d_att[((size_t)b*NN + i0)*NN + idx];
        __syncthreads();
        ull acc[8];
        #pragma unroll
        for (int r = 0; r < 8; r++) acc[r] = 0ull;
        const float* hb = d_h + b*NN*FOUT;
        #pragma unroll 2
        for (int jq = 0; jq < NN/4; jq++) {
            float h0 = hb[(4*jq+0)*FOUT + tid];
            float h1 = hb[(4*jq+1)*FOUT + tid];
            float h2 = hb[(4*jq+2)*FOUT + tid];
            float h3 = hb[(4*jq+3)*FOUT + tid];
            ull hp0 = pk(h0, h1), hp1 = pk(h2, h3);
            #pragma unroll
            for (int r = 0; r < 8; r++) {
                ulonglong2 av = *reinterpret_cast<const ulonglong2*>(&as[r*NN + 4*jq]);
                fma2(acc[r], av.x, hp0);
                fma2(acc[r], av.y, hp1);
            }
        }
        #pragma unroll
        for (int r = 0; r < 8; r++)
            d_cat[(b*NN + i0 + r)*CATW + 2*CI + tid] = hsum2(acc[r]);
    } else {
        // ---- k5: pre[dir][b,t,c], 16 t-rows per block ----
        int bx2 = blockIdx.x - 256;         // 0..255
        int dir = bx2 >> 7;
        int rem = bx2 & 127;
        int b   = rem >> 3;
        int t0  = (rem & 7) * RPB;
        int c    = tid & 63;
        int quad = tid >> 6;
        float* wT = pool;                   // NN*65
        float* xs = pool + NN*65;           // RPB*NN
        const float* wih = dir ? wih_b : wih_f;
        for (int idx = tid; idx < CI*NN; idx += 256) {
            int cc = idx >> 7, q = idx & 127;
            wT[q*65 + cc] = wih[idx];
        }
        for (int idx = tid; idx < RPB*NN; idx += 256) {
            int r = idx >> 7, q = idx & 127;
            int src = dir ? (NN-1 - (t0+r)) : (t0+r);
            xs[r*NN + q] = d_hn[(b*NN + src)*NN + q];
        }
        __syncthreads();
        float bias = dir ? (bih_b[c] + bhh_b[c]) : (bih_f[c] + bhh_f[c]);
        float acc[4];
        #pragma unroll
        for (int r = 0; r < 4; r++) acc[r] = bias;
        #pragma unroll 2
        for (int qq = 0; qq < NN/4; qq++) {
            float w0 = wT[(4*qq+0)*65 + c];
            float w1 = wT[(4*qq+1)*65 + c];
            float w2 = wT[(4*qq+2)*65 + c];
            float w3 = wT[(4*qq+3)*65 + c];
            #pragma unroll
            for (int r = 0; r < 4; r++) {
                float4 xv = *reinterpret_cast<const float4*>(&xs[(quad*4+r)*NN + 4*qq]);
                acc[r] = fmaf(xv.x, w0, fmaf(xv.y, w1, fmaf(xv.z, w2, fmaf(xv.w, w3, acc[r]))));
            }
        }
        #pragma unroll
        for (int r = 0; r < 4; r++)
            d_pre[dir][(b*NN + t0 + quad*4 + r)*CI + c] = acc[r];
    }
}

// ---------------- K6: serial RNN recurrence (prefetch depth 2) ----------------
__global__ void __launch_bounds__(64) k6_rnn(const float* __restrict__ whh_f,
                                             const float* __restrict__ whh_b)
{
    int dir = blockIdx.x >> 4;
    int b   = blockIdx.x & 15;
    int j   = threadIdx.x;
    const float* whh = dir ? whh_b : whh_f;
    ull w2[32];
    {
        const float4* wr = reinterpret_cast<const float4*>(whh + j*64);
        #pragma unroll
        for (int kk = 0; kk < 16; kk++) {
            float4 wv = wr[kk];
            w2[2*kk]   = pk(wv.x, wv.y);
            w2[2*kk+1] = pk(wv.z, wv.w);
        }
    }
    __shared__ __align__(16) float hbuf[2][64];
    hbuf[0][j] = 0.f;
    const float* pre  = d_pre[dir] + (b*NN)*CI + j;
    float*       outp = d_cat + (b*NN)*CATW + dir*CI + j;
    float pv = pre[0];
    float nv = pre[CI];
    __syncthreads();
    #pragma unroll 1
    for (int t = 0; t < NN; t++) {
        int cur = t & 1;
        float nv2 = (t < NN-2) ? pre[(t+2)*CI] : 0.f;   // prefetch 2 steps ahead
        const ulonglong2* h4 = reinterpret_cast<const ulonglong2*>(hbuf[cur]);
        ull a0 = 0ull, a1 = 0ull, a2 = 0ull, a3 = 0ull;
        #pragma unroll
        for (int kk = 0; kk < 16; kk++) {
            ulonglong2 hv = h4[kk];
            ull& acc = (kk & 3) == 0 ? a0 : ((kk & 3) == 1 ? a1 : ((kk & 3) == 2 ? a2 : a3));
            fma2(acc, w2[2*kk],   hv.x);
            fma2(acc, w2[2*kk+1], hv.y);
        }
        float dot = hsum2(add2(add2(a0, a1), add2(a2, a3)));
        float sarg = pv + dot;
        float ee = __expf(2.f * sarg);
        float th = 1.f - __fdividef(2.f, ee + 1.f);
        pv = nv; nv = nv2;
        hbuf[cur ^ 1][j] = th;
        int tt = dir ? (NN-1 - t) : t;
        outp[tt*CATW] = lrelu(th);
        __syncthreads();
    }
}

// ---------------- K8: out = elu(cat @ fco_w + fco_b) ----------------
__global__ void __launch_bounds__(256) k8_out(const float* __restrict__ fco_w,
                                              const float* __restrict__ fco_b,
                                              float* __restrict__ out)
{
    int c    = threadIdx.x;
    int row0 = blockIdx.x * RPB;
    __shared__ __align__(16) float cs[RPB*CATW];
    {
        const float4* src = reinterpret_cast<const float4*>(d_cat + row0*CATW);
        float4* dst = reinterpret_cast<float4*>(cs);
        for (int t = c; t < RPB*CATW/4; t += 256) dst[t] = src[t];
    }
    __syncthreads();
    float bias = fco_b[c];
    ull acc[RPB];
    #pragma unroll
    for (int r = 0; r < RPB; r++) acc[r] = 0ull;
    #pragma unroll 2
    for (int qq = 0; qq < CATW/4; qq++) {
        float w0 = fco_w[(4*qq+0)*LL1 + c];
        float w1 = fco_w[(4*qq+1)*LL1 + c];
        float w2 = fco_w[(4*qq+2)*LL1 + c];
        float w3 = fco_w[(4*qq+3)*LL1 + c];
        ull wp0 = pk(w0, w1), wp1 = pk(w2, w3);
        #pragma unroll
        for (int r = 0; r < RPB; r++) {
            ulonglong2 cv = *reinterpret_cast<const ulonglong2*>(&cs[r*CATW + 4*qq]);
            fma2(acc[r], cv.x, wp0);
            fma2(acc[r], cv.y, wp1);
        }
    }
    #pragma unroll
    for (int r = 0; r < RPB; r++) {
        float v = hsum2(acc[r]) + bias;
        out[(row0+r)*LL1 + c] = v > 0.f ? v : expm1f(v);
    }
}

// ---------------- launch ----------------
extern "C" void kernel_launch(void* const* d_in, const int* in_sizes, int n_in,
                              void* d_out, int out_size)
{
    const float* x     = (const float*)d_in[0];
    const int*   adj   = (const int*)  d_in[1];
    const float* wedge = (const float*)d_in[2];
    const float* W     = (const float*)d_in[3];
    const float* a     = (const float*)d_in[4];
    const float* wfc_w = (const float*)d_in[5];
    const float* wfc_b = (const float*)d_in[6];
    const float* fc_w  = (const float*)d_in[7];
    const float* fc_b  = (const float*)d_in[8];
    const float* fcc_w = (const float*)d_in[9];
    const float* fcc_b = (const float*)d_in[10];
    const float* wih_f = (const float*)d_in[11];
    const float* whh_f = (const float*)d_in[12];
    const float* bih_f = (const float*)d_in[13];
    const float* bhh_f = (const float*)d_in[14];
    const float* wih_b = (const float*)d_in[15];
    const float* whh_b = (const float*)d_in[16];
    const float* bih_b = (const float*)d_in[17];
    const float* bhh_b = (const float*)d_in[18];
    const float* fco_w = (const float*)d_in[19];
    const float* fco_b = (const float*)d_in[20];
    float* out = (float*)d_out;

    K1    <<<128 + 1024, 256>>>(x, W, a, wedge, wfc_w, wfc_b, fc_w);
    k3_red<<<BB*NN,       64>>>(fc_w, fcc_w);
    k4b   <<<BB*NN,       NN>>>(adj, fc_b, fcc_b);
    kB    <<<512,        256>>>(wih_f, bih_f, bhh_f, wih_b, bih_b, bhh_b);
    k6_rnn<<<2*BB,        64>>>(whh_f, whh_b);
    k8_out<<<BB*NN/RPB,  256>>>(fco_w, fco_b, out);
}